// round 14
// baseline (speedup 1.0000x reference)
#include <cuda_runtime.h>
#include <cuda_fp16.h>
#include <math.h>
#include <stdint.h>

#define N_ROWS 32768
#define D_IN   3000
#define KPAD1  3072
#define H0     1024
#define H1     256
#define K_CL   20

#define NSLICE     4
#define SLICE_ROWS (N_ROWS / NSLICE)    // 8192
#define SLICE_MT   (SLICE_ROWS / 128)   // 64 M-tiles per slice

// ---------------- scratch (static device arrays; no allocs) ----------------
__device__ __align__(16) __half g_xh[(size_t)N_ROWS * KPAD1];
__device__ __align__(16) __half g_w1t[(size_t)H0 * KPAD1];
__device__ __align__(16) __half g_hh[(size_t)N_ROWS * H0];
__device__ __align__(16) __half g_w2t[(size_t)H1 * H0];

// ---------------- helpers ----------------
__device__ __forceinline__ uint32_t smem_u32(const void* p) {
    uint32_t a;
    asm("{ .reg .u64 t; cvta.to.shared.u64 t, %1; cvt.u32.u64 %0, t; }" : "=r"(a) : "l"(p));
    return a;
}
__device__ __forceinline__ void cp_async16(uint32_t s, const void* g) {
    asm volatile("cp.async.cg.shared.global [%0], [%1], 16;" :: "r"(s), "l"(g));
}
__device__ __forceinline__ void cp_commit() {
    asm volatile("cp.async.commit_group;" ::: "memory");
}
template <int N>
__device__ __forceinline__ void cp_wait() {
    asm volatile("cp.async.wait_group %0;" :: "n"(N) : "memory");
}
__device__ __forceinline__ void ldm_x4(uint32_t* r, uint32_t addr) {
    asm volatile("ldmatrix.sync.aligned.m8n8.x4.shared.b16 {%0,%1,%2,%3}, [%4];"
        : "=r"(r[0]), "=r"(r[1]), "=r"(r[2]), "=r"(r[3]) : "r"(addr));
}
__device__ __forceinline__ void mma_f16(float* c, const uint32_t* a, const uint32_t* b) {
    asm volatile(
        "mma.sync.aligned.m16n8k16.row.col.f32.f16.f16.f32 "
        "{%0,%1,%2,%3}, {%4,%5,%6,%7}, {%8,%9}, {%0,%1,%2,%3};"
        : "+f"(c[0]), "+f"(c[1]), "+f"(c[2]), "+f"(c[3])
        : "r"(a[0]), "r"(a[1]), "r"(a[2]), "r"(a[3]), "r"(b[0]), "r"(b[1]));
}

// ---------------- preprocess kernels ----------------
// x [rowBase .. rowBase+SLICE_ROWS) fp32 -> xh fp16 padded, wide streaming.
#define CVT_U_PER_ROW (KPAD1 / 4)   // 768 float4-units per padded row
__global__ __launch_bounds__(256)
void convert_x_kernel(const float* __restrict__ x,
                      __half* __restrict__ xh,
                      int rowBase)
{
    const int64_t total  = (int64_t)SLICE_ROWS * CVT_U_PER_ROW;
    const int64_t stride = (int64_t)gridDim.x * blockDim.x;
    for (int64_t u = (int64_t)blockIdx.x * blockDim.x + threadIdx.x;
         u < total; u += stride) {
        const int r  = (int)(u / CVT_U_PER_ROW);
        const int c4 = (int)(u - (int64_t)r * CVT_U_PER_ROW);   // 0..767
        const int row = rowBase + r;
        __half2 h0, h1;
        if (c4 < D_IN / 4) {
            const float4 v = *reinterpret_cast<const float4*>(
                x + (size_t)row * D_IN + c4 * 4);
            h0 = __floats2half2_rn(v.x, v.y);
            h1 = __floats2half2_rn(v.z, v.w);
        } else {
            h0 = __halves2half2(__float2half_rn(0.f), __float2half_rn(0.f));
            h1 = h0;
        }
        uint2 o;
        o.x = *reinterpret_cast<uint32_t*>(&h0);
        o.y = *reinterpret_cast<uint32_t*>(&h1);
        *reinterpret_cast<uint2*>(xh + (size_t)row * KPAD1 + c4 * 4) = o;
    }
}

// W [K, N] fp32 -> Wt [N, Kpad] fp16 (transposed, zero-padded K)
__global__ __launch_bounds__(256)
void transpose_kernel(const float* __restrict__ W,
                      __half* __restrict__ T,
                      int K, int N, int Kpad)
{
    __shared__ float s[32][33];
    const int k0 = blockIdx.x * 32;
    const int n0 = blockIdx.y * 32;
    const int tx = threadIdx.x, ty = threadIdx.y;
    #pragma unroll
    for (int j = 0; j < 32; j += 8) {
        int k = k0 + ty + j;
        s[ty + j][tx] = (k < K) ? W[(size_t)k * N + n0 + tx] : 0.0f;
    }
    __syncthreads();
    #pragma unroll
    for (int j = 0; j < 32; j += 8) {
        int n = n0 + ty + j;
        int kk = k0 + tx;
        T[(size_t)n * Kpad + kk] = __float2half_rn(s[tx][ty + j]);
    }
}

// ---------------- HMMA single-pass fp16 GEMM (R12 winner, + mOff) ----------
#define TILE_A   16384
#define STAGE_B  32768
#define NSTAGE   3
#define GEMM_SMEM (NSTAGE * STAGE_B)   // 98304

// EPI=0: bias+SiLU -> fp16.  EPI=1: bias -> fp32.
template <int EPI>
__global__ __launch_bounds__(256, 2)
void gemm_mma_kernel(const __half* __restrict__ A,
                     const __half* __restrict__ B,
                     const float* __restrict__ bias,
                     __half* __restrict__ OutH,
                     float* __restrict__ OutF,
                     int Kpad, int NC, int ldOut, int mOff)
{
    extern __shared__ char smem[];
    const uint32_t sbase = smem_u32(smem);
    const int tid  = threadIdx.x;
    const int wid  = tid >> 5;
    const int lane = tid & 31;
    const int mBase = (blockIdx.y + mOff) * 128;
    const int nBase = blockIdx.x * 128;
    const int warpM = (wid & 1) * 64;    // 0 / 64
    const int warpN = (wid >> 1) * 32;   // 0..96

    // ---- per-thread load geometry (constant across chunks) ----
    const int row_ld = tid >> 3;          // 0..31
    const int c16    = tid & 7;           // 16B column
    const uint32_t swB = (uint32_t)(row_ld * 128 + ((c16 * 16) ^ ((row_ld & 7) << 4)));
    const char* gA = (const char*)(A + (size_t)(mBase + row_ld) * Kpad) + c16 * 16;
    const char* gB = (const char*)(B + (size_t)(nBase + row_ld) * Kpad) + c16 * 16;
    const size_t itStride = (size_t)32 * Kpad * sizeof(__half);   // 32 rows down

    // ---- per-warp ldmatrix offsets, fully precomputed ----
    const int aRowIn = lane & 15;
    const int kHalf  = (lane >> 4) << 4;  // 0 / 16 bytes
    uint32_t offA[4][4], offB[2][4];
    #pragma unroll
    for (int mt = 0; mt < 4; mt++) {
        int row = warpM + mt * 16 + aRowIn;
        int xr = (row & 7) << 4;
        #pragma unroll
        for (int ks = 0; ks < 4; ks++)
            offA[mt][ks] = (uint32_t)(row * 128 + ((ks * 32 + kHalf) ^ xr));
    }
    #pragma unroll
    for (int nt2 = 0; nt2 < 2; nt2++) {
        int row = warpN + nt2 * 16 + aRowIn;
        int xr = (row & 7) << 4;
        #pragma unroll
        for (int ks = 0; ks < 4; ks++)
            offB[nt2][ks] = (uint32_t)(row * 128 + ((ks * 32 + kHalf) ^ xr));
    }

    float acc[4][4][4];
    #pragma unroll
    for (int i = 0; i < 4; i++)
        #pragma unroll
        for (int j = 0; j < 4; j++)
            #pragma unroll
            for (int k = 0; k < 4; k++)
                acc[i][j][k] = 0.0f;

    auto load_stage = [&](int stage) {
        const uint32_t st = sbase + stage * STAGE_B;
        #pragma unroll
        for (int it = 0; it < 4; it++)
            cp_async16(st + swB + it * 4096, gA + it * itStride);
        #pragma unroll
        for (int it = 0; it < 4; it++)
            cp_async16(st + TILE_A + swB + it * 4096, gB + it * itStride);
        gA += 128; gB += 128;
        cp_commit();
    };
    auto load_part = [&](int stage, int part) {
        const uint32_t st = sbase + stage * STAGE_B;
        cp_async16(st + swB + part * 4096, gA + part * itStride);
        cp_async16(st + TILE_A + swB + part * 4096, gB + part * itStride);
    };

    load_stage(0);
    load_stage(1);

    int sCompute = 0, sLoad = 2;
    for (int c = 0; c < NC; c++) {
        if (c == NC - 1) cp_wait<0>(); else cp_wait<1>();
        __syncthreads();

        const bool doLoad = (c + 2 < NC);
        const uint32_t st = sbase + sCompute * STAGE_B;
        if (++sCompute == NSTAGE) sCompute = 0;

        #pragma unroll
        for (int ks = 0; ks < 4; ks++) {
            uint32_t fa[4][4], fb[4][2];
            #pragma unroll
            for (int mt = 0; mt < 4; mt++)
                ldm_x4(fa[mt], st + offA[mt][ks]);
            #pragma unroll
            for (int nt2 = 0; nt2 < 2; nt2++) {
                uint32_t r[4];
                ldm_x4(r, st + TILE_A + offB[nt2][ks]);
                fb[nt2 * 2][0] = r[0]; fb[nt2 * 2][1] = r[2];
                fb[nt2 * 2 + 1][0] = r[1]; fb[nt2 * 2 + 1][1] = r[3];
            }
            if (doLoad) load_part(sLoad, ks);
            #pragma unroll
            for (int mt = 0; mt < 4; mt++)
                #pragma unroll
                for (int nt = 0; nt < 4; nt++)
                    mma_f16(acc[mt][nt], fa[mt], fb[nt]);
        }
        if (doLoad) {
            gA += 128; gB += 128;
            cp_commit();
            if (++sLoad == NSTAGE) sLoad = 0;
        }
    }

    // ---- epilogue ----
    const int rBase = mBase + warpM + (lane >> 2);
    const int cBase = nBase + warpN + (lane & 3) * 2;

    #pragma unroll
    for (int mt = 0; mt < 4; mt++) {
        #pragma unroll
        for (int nt = 0; nt < 4; nt++) {
            const int col = cBase + nt * 8;
            const float b0 = bias[col];
            const float b1 = bias[col + 1];
            #pragma unroll
            for (int h = 0; h < 2; h++) {
                const int row = rBase + mt * 16 + h * 8;
                float v0 = acc[mt][nt][2 * h]     + b0;
                float v1 = acc[mt][nt][2 * h + 1] + b1;
                if (EPI == 0) {
                    v0 = v0 / (1.0f + expf(-v0));
                    v1 = v1 / (1.0f + expf(-v1));
                    *reinterpret_cast<__half2*>(OutH + (size_t)row * ldOut + col) =
                        __halves2half2(__float2half_rn(v0), __float2half_rn(v1));
                } else {
                    *reinterpret_cast<float2*>(OutF + (size_t)row * ldOut + col) = make_float2(v0, v1);
                }
            }
        }
    }
}

// ---------------- soft assignment (V=1 -> q = 1/(1+d2), row-normalized) ----
__global__ __launch_bounds__(256)
void soft_assign_kernel(const float* __restrict__ Z,
                        const float* __restrict__ clusters,
                        float* __restrict__ Q,
                        int rowBase)
{
    __shared__ float sCl[K_CL][H1 + 1];
    const int tid = threadIdx.x;
    for (int i = tid; i < K_CL * H1; i += blockDim.x)
        sCl[i / H1][i % H1] = clusters[i];
    __syncthreads();

    const int warpId = tid >> 5;
    const int lane = tid & 31;
    const int row = rowBase + blockIdx.x * 8 + warpId;

    const float* z = Z + (size_t)row * H1;
    float d2 = 0.0f;
    if (lane < K_CL) {
        #pragma unroll 8
        for (int d = 0; d < H1; d++) {
            float diff = z[d] - sCl[lane][d];
            d2 = fmaf(diff, diff, d2);
        }
    }
    float q = (lane < K_CL) ? 1.0f / (1.0f + d2) : 0.0f;
    float s = q;
    #pragma unroll
    for (int off = 16; off > 0; off >>= 1)
        s += __shfl_xor_sync(0xFFFFFFFFu, s, off);
    if (lane < K_CL)
        Q[(size_t)row * K_CL + lane] = q / s;
}

// ---------------- launch (2-stream sliced pipeline, graph-capturable) -----
extern "C" void kernel_launch(void* const* d_in, const int* in_sizes, int n_in,
                              void* d_out, int out_size)
{
    const float* x        = (const float*)d_in[0];
    const float* W1       = (const float*)d_in[1];
    const float* b1       = (const float*)d_in[2];
    const float* W2       = (const float*)d_in[3];
    const float* b2       = (const float*)d_in[4];
    const float* clusters = (const float*)d_in[5];

    float* z_out = (float*)d_out;
    float* q_out = (float*)d_out + (size_t)N_ROWS * H1;

    __half *xh, *w1t, *hh, *w2t;
    cudaGetSymbolAddress((void**)&xh,  g_xh);
    cudaGetSymbolAddress((void**)&w1t, g_w1t);
    cudaGetSymbolAddress((void**)&hh,  g_hh);
    cudaGetSymbolAddress((void**)&w2t, g_w2t);

    // one-time host-side resources (no device memory involved)
    static cudaStream_t s1;
    static cudaEvent_t evFork, evC[NSLICE], evG1[NSLICE], evJoin;
    static bool inited = false;
    if (!inited) {
        cudaStreamCreateWithFlags(&s1, cudaStreamNonBlocking);
        cudaEventCreateWithFlags(&evFork, cudaEventDisableTiming);
        cudaEventCreateWithFlags(&evJoin, cudaEventDisableTiming);
        for (int i = 0; i < NSLICE; i++) {
            cudaEventCreateWithFlags(&evC[i],  cudaEventDisableTiming);
            cudaEventCreateWithFlags(&evG1[i], cudaEventDisableTiming);
        }
        cudaFuncSetAttribute(gemm_mma_kernel<0>, cudaFuncAttributeMaxDynamicSharedMemorySize, GEMM_SMEM);
        cudaFuncSetAttribute(gemm_mma_kernel<1>, cudaFuncAttributeMaxDynamicSharedMemorySize, GEMM_SMEM);
        inited = true;
    }

    // fork side stream from capture (legacy) stream
    cudaEventRecord(evFork, 0);
    cudaStreamWaitEvent(s1, evFork, 0);

    // s0: weight transposes + convert slice 0
    transpose_kernel<<<dim3(KPAD1 / 32, H0 / 32), dim3(32, 8), 0, 0>>>(W1, w1t, D_IN, H0, KPAD1);
    transpose_kernel<<<dim3(H0 / 32, H1 / 32), dim3(32, 8), 0, 0>>>(W2, w2t, H0, H1, H0);
    convert_x_kernel<<<512, 256, 0, 0>>>(x, xh, 0);

    // s1: convert slices 1..3
    for (int i = 1; i < NSLICE; i++) {
        convert_x_kernel<<<512, 256, 0, s1>>>(x, xh, i * SLICE_ROWS);
        cudaEventRecord(evC[i], s1);
    }

    // s0: GEMM1 slices (each waits for its convert slice)
    for (int i = 0; i < NSLICE; i++) {
        if (i > 0) cudaStreamWaitEvent(0, evC[i], 0);
        gemm_mma_kernel<0><<<dim3(H0 / 128, SLICE_MT), 256, GEMM_SMEM, 0>>>(
            xh, w1t, b1, hh, nullptr, KPAD1, KPAD1 / 64, H0, i * SLICE_MT);
        cudaEventRecord(evG1[i], 0);
    }

    // s1: GEMM2 + soft assignment per slice, overlapping GEMM1's later slices
    for (int i = 0; i < NSLICE; i++) {
        cudaStreamWaitEvent(s1, evG1[i], 0);
        gemm_mma_kernel<1><<<dim3(H1 / 128, SLICE_MT), 256, GEMM_SMEM, s1>>>(
            hh, w2t, b2, nullptr, z_out, H0, H0 / 64, H1, i * SLICE_MT);
        soft_assign_kernel<<<SLICE_ROWS / 8, 256, 0, s1>>>(
            z_out, clusters, q_out, i * SLICE_ROWS);
    }

    // join back to capture stream
    cudaEventRecord(evJoin, s1);
    cudaStreamWaitEvent(0, evJoin, 0);
}

// round 15
// speedup vs baseline: 1.0809x; 1.0809x over previous
#include <cuda_runtime.h>
#include <cuda_fp16.h>
#include <math.h>
#include <stdint.h>

#define N_ROWS 32768
#define D_IN   3000
#define KPAD1  3008              // 47 * 64 — minimal K padding
#define NC1    (KPAD1 / 64)      // 47 K-chunks for GEMM1
#define H0     1024
#define H1     256
#define K_CL   20

// ---------------- scratch (static device arrays; no allocs) ----------------
__device__ __align__(16) __half g_xh[(size_t)N_ROWS * KPAD1];
__device__ __align__(16) __half g_w1t[(size_t)H0 * KPAD1];
__device__ __align__(16) __half g_hh[(size_t)N_ROWS * H0];
__device__ __align__(16) __half g_w2t[(size_t)H1 * H0];

// ---------------- helpers ----------------
__device__ __forceinline__ uint32_t smem_u32(const void* p) {
    uint32_t a;
    asm("{ .reg .u64 t; cvta.to.shared.u64 t, %1; cvt.u32.u64 %0, t; }" : "=r"(a) : "l"(p));
    return a;
}
__device__ __forceinline__ void cp_async16(uint32_t s, const void* g) {
    asm volatile("cp.async.cg.shared.global [%0], [%1], 16;" :: "r"(s), "l"(g));
}
__device__ __forceinline__ void cp_commit() {
    asm volatile("cp.async.commit_group;" ::: "memory");
}
template <int N>
__device__ __forceinline__ void cp_wait() {
    asm volatile("cp.async.wait_group %0;" :: "n"(N) : "memory");
}
__device__ __forceinline__ void ldm_x4(uint32_t* r, uint32_t addr) {
    asm volatile("ldmatrix.sync.aligned.m8n8.x4.shared.b16 {%0,%1,%2,%3}, [%4];"
        : "=r"(r[0]), "=r"(r[1]), "=r"(r[2]), "=r"(r[3]) : "r"(addr));
}
__device__ __forceinline__ void mma_f16(float* c, const uint32_t* a, const uint32_t* b) {
    asm volatile(
        "mma.sync.aligned.m16n8k16.row.col.f32.f16.f16.f32 "
        "{%0,%1,%2,%3}, {%4,%5,%6,%7}, {%8,%9}, {%0,%1,%2,%3};"
        : "+f"(c[0]), "+f"(c[1]), "+f"(c[2]), "+f"(c[3])
        : "r"(a[0]), "r"(a[1]), "r"(a[2]), "r"(a[3]), "r"(b[0]), "r"(b[1]));
}

// ---------------- preprocess kernels ----------------
// x [N_ROWS, D_IN] fp32 -> xh [N_ROWS, KPAD1] fp16.
// One block per row; 752 float4-units per row (750 real + 2 zero), no divides.
#define CVT_U_PER_ROW (KPAD1 / 4)   // 752
__global__ __launch_bounds__(256)
void convert_x_kernel(const float* __restrict__ x,
                      __half* __restrict__ xh)
{
    const int row = blockIdx.x;
    const float* src = x + (size_t)row * D_IN;
    __half* dst = xh + (size_t)row * KPAD1;
    #pragma unroll 1
    for (int u = threadIdx.x; u < CVT_U_PER_ROW; u += 256) {
        __half2 h0, h1;
        if (u < D_IN / 4) {
            const float4 v = *reinterpret_cast<const float4*>(src + u * 4);
            h0 = __floats2half2_rn(v.x, v.y);
            h1 = __floats2half2_rn(v.z, v.w);
        } else {
            h0 = __halves2half2(__float2half_rn(0.f), __float2half_rn(0.f));
            h1 = h0;
        }
        uint2 o;
        o.x = *reinterpret_cast<uint32_t*>(&h0);
        o.y = *reinterpret_cast<uint32_t*>(&h1);
        *reinterpret_cast<uint2*>(dst + u * 4) = o;
    }
}

// W [K, N] fp32 -> Wt [N, Kpad] fp16 (transposed, zero-padded K)
__global__ __launch_bounds__(256)
void transpose_kernel(const float* __restrict__ W,
                      __half* __restrict__ T,
                      int K, int N, int Kpad)
{
    __shared__ float s[32][33];
    const int k0 = blockIdx.x * 32;
    const int n0 = blockIdx.y * 32;
    const int tx = threadIdx.x, ty = threadIdx.y;
    #pragma unroll
    for (int j = 0; j < 32; j += 8) {
        int k = k0 + ty + j;
        s[ty + j][tx] = (k < K) ? W[(size_t)k * N + n0 + tx] : 0.0f;
    }
    __syncthreads();
    #pragma unroll
    for (int j = 0; j < 32; j += 8) {
        int n = n0 + ty + j;
        int kk = k0 + tx;
        if (kk < Kpad)
            T[(size_t)n * Kpad + kk] = __float2half_rn(s[tx][ty + j]);
    }
}

// ---------------- HMMA single-pass fp16 GEMM (R12 winner) ----------------
// CTA tile 128x128, warp tile 64x32 (8 warps, 2x4), K-chunk 64 fp16.
// 3 stages x 32KB -> 2 CTAs/SM; next-stage cp.async issued in quarters
// inside the ks-steps to avoid the post-barrier LSU convoy.
#define TILE_A   16384
#define STAGE_B  32768
#define NSTAGE   3
#define GEMM_SMEM (NSTAGE * STAGE_B)   // 98304

// EPI=0: bias+SiLU -> fp16.  EPI=1: bias -> fp32.
template <int EPI>
__global__ __launch_bounds__(256, 2)
void gemm_mma_kernel(const __half* __restrict__ A,
                     const __half* __restrict__ B,
                     const float* __restrict__ bias,
                     __half* __restrict__ OutH,
                     float* __restrict__ OutF,
                     int Kpad, int NC, int ldOut)
{
    extern __shared__ char smem[];
    const uint32_t sbase = smem_u32(smem);
    const int tid  = threadIdx.x;
    const int wid  = tid >> 5;
    const int lane = tid & 31;
    const int mBase = blockIdx.y * 128;
    const int nBase = blockIdx.x * 128;
    const int warpM = (wid & 1) * 64;    // 0 / 64
    const int warpN = (wid >> 1) * 32;   // 0..96

    // ---- per-thread load geometry (constant across chunks) ----
    const int row_ld = tid >> 3;          // 0..31
    const int c16    = tid & 7;           // 16B column
    const uint32_t swB = (uint32_t)(row_ld * 128 + ((c16 * 16) ^ ((row_ld & 7) << 4)));
    const char* gA = (const char*)(A + (size_t)(mBase + row_ld) * Kpad) + c16 * 16;
    const char* gB = (const char*)(B + (size_t)(nBase + row_ld) * Kpad) + c16 * 16;
    const size_t itStride = (size_t)32 * Kpad * sizeof(__half);   // 32 rows down

    // ---- per-warp ldmatrix offsets, fully precomputed ----
    const int aRowIn = lane & 15;
    const int kHalf  = (lane >> 4) << 4;  // 0 / 16 bytes
    uint32_t offA[4][4], offB[2][4];
    #pragma unroll
    for (int mt = 0; mt < 4; mt++) {
        int row = warpM + mt * 16 + aRowIn;
        int xr = (row & 7) << 4;
        #pragma unroll
        for (int ks = 0; ks < 4; ks++)
            offA[mt][ks] = (uint32_t)(row * 128 + ((ks * 32 + kHalf) ^ xr));
    }
    #pragma unroll
    for (int nt2 = 0; nt2 < 2; nt2++) {
        int row = warpN + nt2 * 16 + aRowIn;
        int xr = (row & 7) << 4;
        #pragma unroll
        for (int ks = 0; ks < 4; ks++)
            offB[nt2][ks] = (uint32_t)(row * 128 + ((ks * 32 + kHalf) ^ xr));
    }

    float acc[4][4][4];
    #pragma unroll
    for (int i = 0; i < 4; i++)
        #pragma unroll
        for (int j = 0; j < 4; j++)
            #pragma unroll
            for (int k = 0; k < 4; k++)
                acc[i][j][k] = 0.0f;

    auto load_stage = [&](int stage) {
        const uint32_t st = sbase + stage * STAGE_B;
        #pragma unroll
        for (int it = 0; it < 4; it++)
            cp_async16(st + swB + it * 4096, gA + it * itStride);
        #pragma unroll
        for (int it = 0; it < 4; it++)
            cp_async16(st + TILE_A + swB + it * 4096, gB + it * itStride);
        gA += 128; gB += 128;
        cp_commit();
    };
    auto load_part = [&](int stage, int part) {
        const uint32_t st = sbase + stage * STAGE_B;
        cp_async16(st + swB + part * 4096, gA + part * itStride);
        cp_async16(st + TILE_A + swB + part * 4096, gB + part * itStride);
    };

    load_stage(0);
    load_stage(1);

    int sCompute = 0, sLoad = 2;
    for (int c = 0; c < NC; c++) {
        if (c == NC - 1) cp_wait<0>(); else cp_wait<1>();
        __syncthreads();

        const bool doLoad = (c + 2 < NC);
        const uint32_t st = sbase + sCompute * STAGE_B;
        if (++sCompute == NSTAGE) sCompute = 0;

        #pragma unroll
        for (int ks = 0; ks < 4; ks++) {
            uint32_t fa[4][4], fb[4][2];
            #pragma unroll
            for (int mt = 0; mt < 4; mt++)
                ldm_x4(fa[mt], st + offA[mt][ks]);
            #pragma unroll
            for (int nt2 = 0; nt2 < 2; nt2++) {
                uint32_t r[4];
                ldm_x4(r, st + TILE_A + offB[nt2][ks]);
                fb[nt2 * 2][0] = r[0]; fb[nt2 * 2][1] = r[2];
                fb[nt2 * 2 + 1][0] = r[1]; fb[nt2 * 2 + 1][1] = r[3];
            }
            if (doLoad) load_part(sLoad, ks);
            #pragma unroll
            for (int mt = 0; mt < 4; mt++)
                #pragma unroll
                for (int nt = 0; nt < 4; nt++)
                    mma_f16(acc[mt][nt], fa[mt], fb[nt]);
        }
        if (doLoad) {
            gA += 128; gB += 128;
            cp_commit();
            if (++sLoad == NSTAGE) sLoad = 0;
        }
    }

    // ---- epilogue ----
    const int rBase = mBase + warpM + (lane >> 2);
    const int cBase = nBase + warpN + (lane & 3) * 2;

    #pragma unroll
    for (int mt = 0; mt < 4; mt++) {
        #pragma unroll
        for (int nt = 0; nt < 4; nt++) {
            const int col = cBase + nt * 8;
            const float b0 = bias[col];
            const float b1 = bias[col + 1];
            #pragma unroll
            for (int h = 0; h < 2; h++) {
                const int row = rBase + mt * 16 + h * 8;
                float v0 = acc[mt][nt][2 * h]     + b0;
                float v1 = acc[mt][nt][2 * h + 1] + b1;
                if (EPI == 0) {
                    v0 = v0 / (1.0f + expf(-v0));
                    v1 = v1 / (1.0f + expf(-v1));
                    *reinterpret_cast<__half2*>(OutH + (size_t)row * ldOut + col) =
                        __halves2half2(__float2half_rn(v0), __float2half_rn(v1));
                } else {
                    *reinterpret_cast<float2*>(OutF + (size_t)row * ldOut + col) = make_float2(v0, v1);
                }
            }
        }
    }
}

// ---------------- soft assignment (V=1 -> q = 1/(1+d2), row-normalized) ----
__global__ __launch_bounds__(256)
void soft_assign_kernel(const float* __restrict__ Z,
                        const float* __restrict__ clusters,
                        float* __restrict__ Q)
{
    __shared__ float sCl[K_CL][H1 + 1];
    const int tid = threadIdx.x;
    for (int i = tid; i < K_CL * H1; i += blockDim.x)
        sCl[i / H1][i % H1] = clusters[i];
    __syncthreads();

    const int warpId = tid >> 5;
    const int lane = tid & 31;
    const int row = blockIdx.x * 8 + warpId;
    if (row >= N_ROWS) return;

    const float* z = Z + (size_t)row * H1;
    float d2 = 0.0f;
    if (lane < K_CL) {
        #pragma unroll 8
        for (int d = 0; d < H1; d++) {
            float diff = z[d] - sCl[lane][d];
            d2 = fmaf(diff, diff, d2);
        }
    }
    float q = (lane < K_CL) ? 1.0f / (1.0f + d2) : 0.0f;
    float s = q;
    #pragma unroll
    for (int off = 16; off > 0; off >>= 1)
        s += __shfl_xor_sync(0xFFFFFFFFu, s, off);
    if (lane < K_CL)
        Q[(size_t)row * K_CL + lane] = q / s;
}

// ---------------- launch ----------------
extern "C" void kernel_launch(void* const* d_in, const int* in_sizes, int n_in,
                              void* d_out, int out_size)
{
    const float* x        = (const float*)d_in[0];
    const float* W1       = (const float*)d_in[1];
    const float* b1       = (const float*)d_in[2];
    const float* W2       = (const float*)d_in[3];
    const float* b2       = (const float*)d_in[4];
    const float* clusters = (const float*)d_in[5];

    float* z_out = (float*)d_out;
    float* q_out = (float*)d_out + (size_t)N_ROWS * H1;

    __half *xh, *w1t, *hh, *w2t;
    cudaGetSymbolAddress((void**)&xh,  g_xh);
    cudaGetSymbolAddress((void**)&w1t, g_w1t);
    cudaGetSymbolAddress((void**)&hh,  g_hh);
    cudaGetSymbolAddress((void**)&w2t, g_w2t);

    static cudaStream_t s1;
    static cudaEvent_t evFork, evJoin;
    static bool inited = false;
    if (!inited) {
        cudaStreamCreateWithFlags(&s1, cudaStreamNonBlocking);
        cudaEventCreateWithFlags(&evFork, cudaEventDisableTiming);
        cudaEventCreateWithFlags(&evJoin, cudaEventDisableTiming);
        cudaFuncSetAttribute(gemm_mma_kernel<0>, cudaFuncAttributeMaxDynamicSharedMemorySize, GEMM_SMEM);
        cudaFuncSetAttribute(gemm_mma_kernel<1>, cudaFuncAttributeMaxDynamicSharedMemorySize, GEMM_SMEM);
        inited = true;
    }

    // fork: weight transposes (s1) overlap x conversion (s0)
    cudaEventRecord(evFork, 0);
    cudaStreamWaitEvent(s1, evFork, 0);

    convert_x_kernel<<<N_ROWS, 256, 0, 0>>>(x, xh);

    transpose_kernel<<<dim3((KPAD1 + 31) / 32, H0 / 32), dim3(32, 8), 0, s1>>>(W1, w1t, D_IN, H0, KPAD1);
    transpose_kernel<<<dim3(H0 / 32, H1 / 32), dim3(32, 8), 0, s1>>>(W2, w2t, H0, H1, H0);

    cudaEventRecord(evJoin, s1);
    cudaStreamWaitEvent(0, evJoin, 0);

    // GEMM1: H = silu(x @ W1 + b1) -> fp16   (47 K-chunks, no zero chunk)
    gemm_mma_kernel<0><<<dim3(H0 / 128, N_ROWS / 128), 256, GEMM_SMEM, 0>>>(
        xh, w1t, b1, hh, nullptr, KPAD1, NC1, H0);

    // GEMM2: z = H @ W2 + b2 -> fp32
    gemm_mma_kernel<1><<<dim3(H1 / 128, N_ROWS / 128), 256, GEMM_SMEM, 0>>>(
        hh, w2t, b2, nullptr, z_out, H0, H0 / 64, H1);

    // soft assignment
    soft_assign_kernel<<<N_ROWS / 8, 256, 0, 0>>>(z_out, clusters, q_out);
}